// round 14
// baseline (speedup 1.0000x reference)
#include <cuda_runtime.h>
#include <cuda_bf16.h>
#include <cstdint>

#define MDIM 8192
#define KDIM 4096
#define NDIM 11008

// ---------------- static device scratch (no runtime allocation) ----------------
__device__ __align__(256) __nv_bfloat16 g_A[(size_t)MDIM * KDIM];   // 67 MB
__device__ __align__(256) __nv_bfloat16 g_W[(size_t)NDIM * KDIM];   // 90 MB
__device__ __align__(256) float g_xs[MDIM];
__device__ __align__(256) float g_scol[NDIM];
__device__ __align__(256) int   g_mask[KDIM];

// ---------------- PTX helpers ----------------
__device__ __forceinline__ uint32_t smem_u32(const void* p) {
    uint32_t a;
    asm("{ .reg .u64 t; cvta.to.shared.u64 t, %1; cvt.u32.u64 %0, t; }" : "=r"(a) : "l"(p));
    return a;
}
#define SWZ(o) ((o) ^ (((o) >> 3) & 0x70))

__device__ __forceinline__ void cp16(uint32_t s, const void* g) {
    asm volatile("cp.async.cg.shared.global [%0], [%1], 16;" :: "r"(s), "l"(g));
}
#define CP_COMMIT()  asm volatile("cp.async.commit_group;")
#define CP_WAIT(n)   asm volatile("cp.async.wait_group %0;" :: "n"(n))

__device__ __forceinline__ void ldsm_x4(uint32_t& r0, uint32_t& r1, uint32_t& r2,
                                        uint32_t& r3, uint32_t a) {
    asm volatile("ldmatrix.sync.aligned.m8n8.x4.shared.b16 {%0,%1,%2,%3}, [%4];"
                 : "=r"(r0), "=r"(r1), "=r"(r2), "=r"(r3) : "r"(a));
}
__device__ __forceinline__ void mma_bf16(float* c, const uint32_t* a, const uint32_t* b) {
    asm volatile("mma.sync.aligned.m16n8k16.row.col.f32.bf16.bf16.f32 "
        "{%0,%1,%2,%3}, {%4,%5,%6,%7}, {%8,%9}, {%0,%1,%2,%3};"
        : "+f"(c[0]), "+f"(c[1]), "+f"(c[2]), "+f"(c[3])
        : "r"(a[0]), "r"(a[1]), "r"(a[2]), "r"(a[3]), "r"(b[0]), "r"(b[1]));
}

// ---------------- preprocessing ----------------
__global__ void zmask_k() {
    int i = blockIdx.x * blockDim.x + threadIdx.x;
    if (i < KDIM) g_mask[i] = 0;
}

__global__ void colmask_k(const float* __restrict__ x, const float* __restrict__ sg) {
    float s = *sg;
    const float4* x4 = reinterpret_cast<const float4*>(x);
    size_t n4 = (size_t)MDIM * KDIM / 4;
    for (size_t i = (size_t)blockIdx.x * blockDim.x + threadIdx.x; i < n4;
         i += (size_t)gridDim.x * blockDim.x) {
        float4 v = x4[i];
        int k0 = (int)((i * 4) & (KDIM - 1));
        if (fabsf(v.x) > s) atomicOr(&g_mask[k0 + 0], 1);
        if (fabsf(v.y) > s) atomicOr(&g_mask[k0 + 1], 1);
        if (fabsf(v.z) > s) atomicOr(&g_mask[k0 + 2], 1);
        if (fabsf(v.w) > s) atomicOr(&g_mask[k0 + 3], 1);
    }
}

// per weight row: scol = max|w|/64 ; Qw = rint(w/scol) as bf16 (exact: integers <= 64)
__global__ void __launch_bounds__(256) wquant_k(const float* __restrict__ w) {
    int n = blockIdx.x, t = threadIdx.x;
    const float4* row = reinterpret_cast<const float4*>(w + (size_t)n * KDIM);
    float4 v[4]; float mx = 0.f;
#pragma unroll
    for (int i = 0; i < 4; i++) {
        v[i] = row[t + i * 256];
        mx = fmaxf(mx, fmaxf(fmaxf(fabsf(v[i].x), fabsf(v[i].y)),
                             fmaxf(fabsf(v[i].z), fabsf(v[i].w))));
    }
#pragma unroll
    for (int o = 16; o > 0; o >>= 1) mx = fmaxf(mx, __shfl_xor_sync(0xffffffffu, mx, o));
    __shared__ float wm[8];
    if ((t & 31) == 0) wm[t >> 5] = mx;
    __syncthreads();
    float m2 = wm[0];
#pragma unroll
    for (int i = 1; i < 8; i++) m2 = fmaxf(m2, wm[i]);
    float scale = m2 * (1.f / 64.f);
    float inv = 1.f / scale;
    if (t == 0) g_scol[n] = scale;
    __nv_bfloat162* orow = reinterpret_cast<__nv_bfloat162*>(g_W + (size_t)n * KDIM);
#pragma unroll
    for (int i = 0; i < 4; i++) {
        int f = t + i * 256;
        orow[2 * f + 0] = __floats2bfloat162_rn(rintf(v[i].x * inv), rintf(v[i].y * inv));
        orow[2 * f + 1] = __floats2bfloat162_rn(rintf(v[i].z * inv), rintf(v[i].w * inv));
    }
}

// per x row: xs = max(max|x_in|/127, 1e-8); A = mask? x/xs : rint(x/xs) as bf16
__global__ void __launch_bounds__(256) aquant_k(const float* __restrict__ x) {
    int m = blockIdx.x, t = threadIdx.x;
    const float4* row = reinterpret_cast<const float4*>(x + (size_t)m * KDIM);
    float4 v[4]; int msk[16]; float mx = 0.f;
#pragma unroll
    for (int i = 0; i < 4; i++) {
        int f = t + i * 256;
        v[i] = row[f];
        int kb = f * 4;
        msk[4 * i + 0] = g_mask[kb + 0]; msk[4 * i + 1] = g_mask[kb + 1];
        msk[4 * i + 2] = g_mask[kb + 2]; msk[4 * i + 3] = g_mask[kb + 3];
        if (!msk[4 * i + 0]) mx = fmaxf(mx, fabsf(v[i].x));
        if (!msk[4 * i + 1]) mx = fmaxf(mx, fabsf(v[i].y));
        if (!msk[4 * i + 2]) mx = fmaxf(mx, fabsf(v[i].z));
        if (!msk[4 * i + 3]) mx = fmaxf(mx, fabsf(v[i].w));
    }
#pragma unroll
    for (int o = 16; o > 0; o >>= 1) mx = fmaxf(mx, __shfl_xor_sync(0xffffffffu, mx, o));
    __shared__ float wm[8];
    if ((t & 31) == 0) wm[t >> 5] = mx;
    __syncthreads();
    float m2 = wm[0];
#pragma unroll
    for (int i = 1; i < 8; i++) m2 = fmaxf(m2, wm[i]);
    float s = fmaxf(m2 * (1.f / 127.f), 1e-8f);
    float inv = 1.f / s;
    if (t == 0) g_xs[m] = s;
    __nv_bfloat162* orow = reinterpret_cast<__nv_bfloat162*>(g_A + (size_t)m * KDIM);
#pragma unroll
    for (int i = 0; i < 4; i++) {
        int f = t + i * 256;
        float a0 = v[i].x * inv; if (!msk[4 * i + 0]) a0 = rintf(a0);
        float a1 = v[i].y * inv; if (!msk[4 * i + 1]) a1 = rintf(a1);
        float a2 = v[i].z * inv; if (!msk[4 * i + 2]) a2 = rintf(a2);
        float a3 = v[i].w * inv; if (!msk[4 * i + 3]) a3 = rintf(a3);
        orow[2 * f + 0] = __floats2bfloat162_rn(a0, a1);
        orow[2 * f + 1] = __floats2bfloat162_rn(a2, a3);
    }
}

// ---------------- HMMA GEMM: CTA 128x256, warp tile 64x64, reg double-buffer ----
#define BM 128
#define BN 256
#define BK 64
#define STAGES 4
#define KBLKS (KDIM / BK)          // 64
#define TM_TILES (MDIM / BM)       // 64
#define TN_TILES (NDIM / BN)       // 43
#define A_BYTES (BM * 128)         // 16 KB
#define B_BYTES (BN * 128)         // 32 KB
#define STAGE_BYTES (A_BYTES + B_BYTES)    // 48 KB
#define SMEM_TOTAL (STAGES * STAGE_BYTES)  // 192 KB

__device__ __forceinline__ void load_stage(uint32_t sb, int s, int kb,
                                           const __nv_bfloat16* __restrict__ Ab,
                                           const __nv_bfloat16* __restrict__ Bb, int t) {
    uint32_t sa = sb + s * STAGE_BYTES;
    const __nv_bfloat16* gA = Ab + kb * BK;
    const __nv_bfloat16* gB = Bb + kb * BK;
#pragma unroll
    for (int i = 0; i < 12; i++) {
        int c = t + i * 256;               // 3072 chunks of 16 B per stage
        int isB = (c >= 1024);
        int cc = isB ? (c - 1024) : c;
        int row = cc >> 3, c16 = cc & 7;   // A rows 0..127, B rows 0..255
        uint32_t soff = sa + (isB ? A_BYTES : 0) + SWZ(row * 128 + c16 * 16);
        const __nv_bfloat16* g = (isB ? gB : gA) + (size_t)row * KDIM + c16 * 8;
        cp16(soff, g);
    }
}

__global__ void __launch_bounds__(256, 1) gemm_k(float* __restrict__ out) {
    extern __shared__ char smem[];
    uint32_t sb = smem_u32(smem);
    int tid = threadIdx.x, wid = tid >> 5, lane = tid & 31;

    // grid swizzle: groups of 8 M-tiles share W traffic in L2
    int pid = blockIdx.x;
    const int GR = 8, per = GR * TN_TILES;
    int gid = pid / per, rem = pid % per;
    int fm = gid * GR;
    int gsz = (TM_TILES - fm < GR) ? (TM_TILES - fm) : GR;
    int tm = fm + rem % gsz;
    int tn = rem / gsz;

    const __nv_bfloat16* Ab = g_A + (size_t)tm * BM * KDIM;
    const __nv_bfloat16* Bb = g_W + (size_t)tn * BN * KDIM;

#pragma unroll
    for (int p = 0; p < STAGES - 1; p++) { load_stage(sb, p, p, Ab, Bb, tid); CP_COMMIT(); }

    int wm = wid & 1, wn = wid >> 1;          // warp tile 64x64 at (wm*64, wn*64)
    float acc[4][8][4];
#pragma unroll
    for (int i = 0; i < 4; i++)
#pragma unroll
        for (int j = 0; j < 8; j++)
#pragma unroll
            for (int k = 0; k < 4; k++) acc[i][j][k] = 0.f;

    // ldmatrix lane addressing (within tile, pre-swizzle)
    int a_row = wm * 64 + (lane & 15);        // + mf*16
    int a_kc  = (lane >> 4) * 8;              // + ks*16
    int b_row = wn * 64 + ((lane >> 4) & 1) * 8 + (lane & 7);  // + p*16
    int b_kc  = ((lane >> 3) & 1) * 8;        // + ks*16

    uint32_t a[2][4][4], b[2][8][2];          // register double buffer over ks

    for (int it = 0; it < KBLKS; ++it) {
        int s = it & (STAGES - 1);
        CP_WAIT(STAGES - 2);                  // k-block `it` resident
        __syncthreads();
        int nb = it + STAGES - 1;
        if (nb < KBLKS) load_stage(sb, nb & (STAGES - 1), nb, Ab, Bb, tid);
        CP_COMMIT();

        uint32_t sa = sb + s * STAGE_BYTES;

        // prefetch fragments for ks=0
#pragma unroll
        for (int mf = 0; mf < 4; mf++)
            ldsm_x4(a[0][mf][0], a[0][mf][1], a[0][mf][2], a[0][mf][3],
                    sa + SWZ((a_row + mf * 16) * 128 + a_kc * 2));
#pragma unroll
        for (int p = 0; p < 4; p++)
            ldsm_x4(b[0][2 * p][0], b[0][2 * p][1], b[0][2 * p + 1][0], b[0][2 * p + 1][1],
                    sa + A_BYTES + SWZ((b_row + p * 16) * 128 + b_kc * 2));

#pragma unroll
        for (int ks = 0; ks < 4; ks++) {
            int cur = ks & 1, nxt = cur ^ 1;
            if (ks < 3) {   // prefetch ks+1 fragments; MMA burst below hides LDS latency
#pragma unroll
                for (int mf = 0; mf < 4; mf++)
                    ldsm_x4(a[nxt][mf][0], a[nxt][mf][1], a[nxt][mf][2], a[nxt][mf][3],
                            sa + SWZ((a_row + mf * 16) * 128 + (a_kc + (ks + 1) * 16) * 2));
#pragma unroll
                for (int p = 0; p < 4; p++)
                    ldsm_x4(b[nxt][2 * p][0], b[nxt][2 * p][1],
                            b[nxt][2 * p + 1][0], b[nxt][2 * p + 1][1],
                            sa + A_BYTES + SWZ((b_row + p * 16) * 128 + (b_kc + (ks + 1) * 16) * 2));
            }
#pragma unroll
            for (int mf = 0; mf < 4; mf++)
#pragma unroll
                for (int nf = 0; nf < 8; nf++)
                    mma_bf16(acc[mf][nf], a[cur][mf], b[cur][nf]);
        }
    }

    // epilogue: y = acc * xs[m] * scol[n]
    int m0 = tm * BM + wm * 64 + (lane >> 2);
    int n0 = tn * BN + wn * 64 + (lane & 3) * 2;
#pragma unroll
    for (int mf = 0; mf < 4; mf++) {
        int r0 = m0 + mf * 16;
        float xs0 = g_xs[r0], xs1 = g_xs[r0 + 8];
#pragma unroll
        for (int nf = 0; nf < 8; nf++) {
            int n = n0 + nf * 8;
            float s0 = g_scol[n], s1 = g_scol[n + 1];
            float2 v0 = { acc[mf][nf][0] * xs0 * s0, acc[mf][nf][1] * xs0 * s1 };
            float2 v1 = { acc[mf][nf][2] * xs1 * s0, acc[mf][nf][3] * xs1 * s1 };
            *reinterpret_cast<float2*>(out + (size_t)r0 * NDIM + n) = v0;
            *reinterpret_cast<float2*>(out + (size_t)(r0 + 8) * NDIM + n) = v1;
        }
    }
}

// ---------------- launcher ----------------
extern "C" void kernel_launch(void* const* d_in, const int* in_sizes, int n_in,
                              void* d_out, int out_size) {
    (void)in_sizes; (void)n_in; (void)out_size;
    const float* x   = (const float*)d_in[0];
    const float* w   = (const float*)d_in[1];
    const float* sig = (const float*)d_in[2];
    float* out = (float*)d_out;

    zmask_k<<<(KDIM + 255) / 256, 256>>>();
    colmask_k<<<2048, 256>>>(x, sig);
    wquant_k<<<NDIM, 256>>>(w);
    aquant_k<<<MDIM, 256>>>(x);

    cudaFuncSetAttribute(gemm_k, cudaFuncAttributeMaxDynamicSharedMemorySize, SMEM_TOTAL);
    gemm_k<<<TM_TILES * TN_TILES, 256, SMEM_TOTAL>>>(out);
}

// round 15
// speedup vs baseline: 1.1438x; 1.1438x over previous
#include <cuda_runtime.h>
#include <cuda_bf16.h>
#include <cstdint>

#define MDIM 8192
#define KDIM 4096
#define NDIM 11008

// ---------------- static device scratch (no runtime allocation) ----------------
__device__ __align__(256) __nv_bfloat16 g_A[(size_t)MDIM * KDIM];   // 67 MB
__device__ __align__(256) __nv_bfloat16 g_W[(size_t)NDIM * KDIM];   // 90 MB
__device__ __align__(256) float g_xs[MDIM];
__device__ __align__(256) float g_scol[NDIM];
__device__ __align__(256) int   g_mask[KDIM];

// ---------------- PTX helpers ----------------
__device__ __forceinline__ uint32_t smem_u32(const void* p) {
    uint32_t a;
    asm("{ .reg .u64 t; cvta.to.shared.u64 t, %1; cvt.u32.u64 %0, t; }" : "=r"(a) : "l"(p));
    return a;
}
#define SWZ(o) ((o) ^ (((o) >> 3) & 0x70))

__device__ __forceinline__ void cp16(uint32_t s, const void* g) {
    asm volatile("cp.async.cg.shared.global [%0], [%1], 16;" :: "r"(s), "l"(g));
}
#define CP_COMMIT()  asm volatile("cp.async.commit_group;")
#define CP_WAIT(n)   asm volatile("cp.async.wait_group %0;" :: "n"(n))

__device__ __forceinline__ void ldsm_x4(uint32_t& r0, uint32_t& r1, uint32_t& r2,
                                        uint32_t& r3, uint32_t a) {
    asm volatile("ldmatrix.sync.aligned.m8n8.x4.shared.b16 {%0,%1,%2,%3}, [%4];"
                 : "=r"(r0), "=r"(r1), "=r"(r2), "=r"(r3) : "r"(a));
}
__device__ __forceinline__ void mma_bf16(float* c, const uint32_t* a, const uint32_t* b) {
    asm volatile("mma.sync.aligned.m16n8k16.row.col.f32.bf16.bf16.f32 "
        "{%0,%1,%2,%3}, {%4,%5,%6,%7}, {%8,%9}, {%0,%1,%2,%3};"
        : "+f"(c[0]), "+f"(c[1]), "+f"(c[2]), "+f"(c[3])
        : "r"(a[0]), "r"(a[1]), "r"(a[2]), "r"(a[3]), "r"(b[0]), "r"(b[1]));
}

// ---------------- preprocessing ----------------
__global__ void zmask_k() {
    int i = blockIdx.x * blockDim.x + threadIdx.x;
    if (i < KDIM) g_mask[i] = 0;
}

__global__ void colmask_k(const float* __restrict__ x, const float* __restrict__ sg) {
    float s = *sg;
    const float4* x4 = reinterpret_cast<const float4*>(x);
    size_t n4 = (size_t)MDIM * KDIM / 4;
    for (size_t i = (size_t)blockIdx.x * blockDim.x + threadIdx.x; i < n4;
         i += (size_t)gridDim.x * blockDim.x) {
        float4 v = x4[i];
        int k0 = (int)((i * 4) & (KDIM - 1));
        if (fabsf(v.x) > s) atomicOr(&g_mask[k0 + 0], 1);
        if (fabsf(v.y) > s) atomicOr(&g_mask[k0 + 1], 1);
        if (fabsf(v.z) > s) atomicOr(&g_mask[k0 + 2], 1);
        if (fabsf(v.w) > s) atomicOr(&g_mask[k0 + 3], 1);
    }
}

// per weight row: scol = max|w|/64 ; Qw = rint(w/scol) as bf16 (exact: integers <= 64)
__global__ void __launch_bounds__(256) wquant_k(const float* __restrict__ w) {
    int n = blockIdx.x, t = threadIdx.x;
    const float4* row = reinterpret_cast<const float4*>(w + (size_t)n * KDIM);
    float4 v[4]; float mx = 0.f;
#pragma unroll
    for (int i = 0; i < 4; i++) {
        v[i] = row[t + i * 256];
        mx = fmaxf(mx, fmaxf(fmaxf(fabsf(v[i].x), fabsf(v[i].y)),
                             fmaxf(fabsf(v[i].z), fabsf(v[i].w))));
    }
#pragma unroll
    for (int o = 16; o > 0; o >>= 1) mx = fmaxf(mx, __shfl_xor_sync(0xffffffffu, mx, o));
    __shared__ float wm[8];
    if ((t & 31) == 0) wm[t >> 5] = mx;
    __syncthreads();
    float m2 = wm[0];
#pragma unroll
    for (int i = 1; i < 8; i++) m2 = fmaxf(m2, wm[i]);
    float scale = m2 * (1.f / 64.f);
    float inv = 1.f / scale;
    if (t == 0) g_scol[n] = scale;
    __nv_bfloat162* orow = reinterpret_cast<__nv_bfloat162*>(g_W + (size_t)n * KDIM);
#pragma unroll
    for (int i = 0; i < 4; i++) {
        int f = t + i * 256;
        orow[2 * f + 0] = __floats2bfloat162_rn(rintf(v[i].x * inv), rintf(v[i].y * inv));
        orow[2 * f + 1] = __floats2bfloat162_rn(rintf(v[i].z * inv), rintf(v[i].w * inv));
    }
}

// per x row: xs = max(max|x_in|/127, 1e-8); A = mask? x/xs : rint(x/xs) as bf16
__global__ void __launch_bounds__(256) aquant_k(const float* __restrict__ x) {
    int m = blockIdx.x, t = threadIdx.x;
    const float4* row = reinterpret_cast<const float4*>(x + (size_t)m * KDIM);
    float4 v[4]; int msk[16]; float mx = 0.f;
#pragma unroll
    for (int i = 0; i < 4; i++) {
        int f = t + i * 256;
        v[i] = row[f];
        int kb = f * 4;
        msk[4 * i + 0] = g_mask[kb + 0]; msk[4 * i + 1] = g_mask[kb + 1];
        msk[4 * i + 2] = g_mask[kb + 2]; msk[4 * i + 3] = g_mask[kb + 3];
        if (!msk[4 * i + 0]) mx = fmaxf(mx, fabsf(v[i].x));
        if (!msk[4 * i + 1]) mx = fmaxf(mx, fabsf(v[i].y));
        if (!msk[4 * i + 2]) mx = fmaxf(mx, fabsf(v[i].z));
        if (!msk[4 * i + 3]) mx = fmaxf(mx, fabsf(v[i].w));
    }
#pragma unroll
    for (int o = 16; o > 0; o >>= 1) mx = fmaxf(mx, __shfl_xor_sync(0xffffffffu, mx, o));
    __shared__ float wm[8];
    if ((t & 31) == 0) wm[t >> 5] = mx;
    __syncthreads();
    float m2 = wm[0];
#pragma unroll
    for (int i = 1; i < 8; i++) m2 = fmaxf(m2, wm[i]);
    float s = fmaxf(m2 * (1.f / 127.f), 1e-8f);
    float inv = 1.f / s;
    if (t == 0) g_xs[m] = s;
    __nv_bfloat162* orow = reinterpret_cast<__nv_bfloat162*>(g_A + (size_t)m * KDIM);
#pragma unroll
    for (int i = 0; i < 4; i++) {
        int f = t + i * 256;
        float a0 = v[i].x * inv; if (!msk[4 * i + 0]) a0 = rintf(a0);
        float a1 = v[i].y * inv; if (!msk[4 * i + 1]) a1 = rintf(a1);
        float a2 = v[i].z * inv; if (!msk[4 * i + 2]) a2 = rintf(a2);
        float a3 = v[i].w * inv; if (!msk[4 * i + 3]) a3 = rintf(a3);
        orow[2 * f + 0] = __floats2bfloat162_rn(a0, a1);
        orow[2 * f + 1] = __floats2bfloat162_rn(a2, a3);
    }
}

// ------- HMMA GEMM: CTA 128x128, warp tile 64x32, 3 stages, 2 CTAs/SM -------
#define BM 128
#define BN 128
#define BK 64
#define STAGES 3
#define KBLKS (KDIM / BK)          // 64
#define TM_TILES (MDIM / BM)       // 64
#define TN_TILES (NDIM / BN)       // 86
#define A_BYTES (BM * 128)         // 16 KB
#define B_BYTES (BN * 128)         // 16 KB
#define STAGE_BYTES (A_BYTES + B_BYTES)    // 32 KB
#define SMEM_TOTAL (STAGES * STAGE_BYTES)  // 96 KB -> 2 CTAs/SM

__device__ __forceinline__ void load_stage(uint32_t sb, int s, int kb,
                                           const __nv_bfloat16* __restrict__ Ab,
                                           const __nv_bfloat16* __restrict__ Bb, int t) {
    uint32_t sa = sb + s * STAGE_BYTES;
    const __nv_bfloat16* gA = Ab + kb * BK;
    const __nv_bfloat16* gB = Bb + kb * BK;
#pragma unroll
    for (int i = 0; i < 8; i++) {
        int c = t + i * 256;               // 2048 chunks of 16 B per stage
        int isB = c >> 10;
        int cc = c & 1023;
        int row = cc >> 3, c16 = cc & 7;   // rows 0..127
        uint32_t soff = sa + isB * A_BYTES + SWZ(row * 128 + c16 * 16);
        const __nv_bfloat16* g = (isB ? gB : gA) + (size_t)row * KDIM + c16 * 8;
        cp16(soff, g);
    }
}

__global__ void __launch_bounds__(256, 2) gemm_k(float* __restrict__ out) {
    extern __shared__ char smem[];
    uint32_t sb = smem_u32(smem);
    int tid = threadIdx.x, wid = tid >> 5, lane = tid & 31;

    // grid swizzle: groups of 8 M-tiles share W traffic in L2
    int pid = blockIdx.x;
    const int GR = 8, per = GR * TN_TILES;
    int gid = pid / per, rem = pid % per;
    int fm = gid * GR;
    int gsz = (TM_TILES - fm < GR) ? (TM_TILES - fm) : GR;
    int tm = fm + rem % gsz;
    int tn = rem / gsz;

    const __nv_bfloat16* Ab = g_A + (size_t)tm * BM * KDIM;
    const __nv_bfloat16* Bb = g_W + (size_t)tn * BN * KDIM;

#pragma unroll
    for (int p = 0; p < STAGES - 1; p++) { load_stage(sb, p, p, Ab, Bb, tid); CP_COMMIT(); }

    int wm = wid & 1, wn = wid >> 1;          // warp tile 64x32 at (wm*64, wn*32)
    float acc[4][4][4];
#pragma unroll
    for (int i = 0; i < 4; i++)
#pragma unroll
        for (int j = 0; j < 4; j++)
#pragma unroll
            for (int k = 0; k < 4; k++) acc[i][j][k] = 0.f;

    // ldmatrix lane addressing (within tile, pre-swizzle)
    int a_row = wm * 64 + (lane & 15);        // + mf*16
    int a_kc  = (lane >> 4) * 8;              // + ks*16
    int b_row = wn * 32 + ((lane >> 4) & 1) * 8 + (lane & 7);  // + p*16
    int b_kc  = ((lane >> 3) & 1) * 8;        // + ks*16

    for (int it = 0; it < KBLKS; ++it) {
        int s = it % STAGES;
        CP_WAIT(STAGES - 2);                  // k-block `it` resident
        __syncthreads();
        int nb = it + STAGES - 1;
        if (nb < KBLKS) load_stage(sb, nb % STAGES, nb, Ab, Bb, tid);
        CP_COMMIT();

        uint32_t sa = sb + s * STAGE_BYTES;
#pragma unroll
        for (int ks = 0; ks < 4; ks++) {
            uint32_t a[4][4], b[4][2];
#pragma unroll
            for (int mf = 0; mf < 4; mf++)
                ldsm_x4(a[mf][0], a[mf][1], a[mf][2], a[mf][3],
                        sa + SWZ((a_row + mf * 16) * 128 + (a_kc + ks * 16) * 2));
#pragma unroll
            for (int p = 0; p < 2; p++) {
                uint32_t r0, r1, r2, r3;
                ldsm_x4(r0, r1, r2, r3,
                        sa + A_BYTES + SWZ((b_row + p * 16) * 128 + (b_kc + ks * 16) * 2));
                b[2 * p][0] = r0; b[2 * p][1] = r1;
                b[2 * p + 1][0] = r2; b[2 * p + 1][1] = r3;
            }
#pragma unroll
            for (int mf = 0; mf < 4; mf++)
#pragma unroll
                for (int nf = 0; nf < 4; nf++)
                    mma_bf16(acc[mf][nf], a[mf], b[nf]);
        }
    }

    // epilogue: y = acc * xs[m] * scol[n]
    int m0 = tm * BM + wm * 64 + (lane >> 2);
    int n0 = tn * BN + wn * 32 + (lane & 3) * 2;
#pragma unroll
    for (int mf = 0; mf < 4; mf++) {
        int r0 = m0 + mf * 16;
        float xs0 = g_xs[r0], xs1 = g_xs[r0 + 8];
#pragma unroll
        for (int nf = 0; nf < 4; nf++) {
            int n = n0 + nf * 8;
            float s0 = g_scol[n], s1 = g_scol[n + 1];
            float2 v0 = { acc[mf][nf][0] * xs0 * s0, acc[mf][nf][1] * xs0 * s1 };
            float2 v1 = { acc[mf][nf][2] * xs1 * s0, acc[mf][nf][3] * xs1 * s1 };
            *reinterpret_cast<float2*>(out + (size_t)r0 * NDIM + n) = v0;
            *reinterpret_cast<float2*>(out + (size_t)(r0 + 8) * NDIM + n) = v1;
        }
    }
}

// ---------------- launcher ----------------
extern "C" void kernel_launch(void* const* d_in, const int* in_sizes, int n_in,
                              void* d_out, int out_size) {
    (void)in_sizes; (void)n_in; (void)out_size;
    const float* x   = (const float*)d_in[0];
    const float* w   = (const float*)d_in[1];
    const float* sig = (const float*)d_in[2];
    float* out = (float*)d_out;

    zmask_k<<<(KDIM + 255) / 256, 256>>>();
    colmask_k<<<2048, 256>>>(x, sig);
    wquant_k<<<NDIM, 256>>>(w);
    aquant_k<<<MDIM, 256>>>(x);

    cudaFuncSetAttribute(gemm_k, cudaFuncAttributeMaxDynamicSharedMemorySize, SMEM_TOTAL);
    gemm_k<<<TM_TILES * TN_TILES, 256, SMEM_TOTAL>>>(out);
}

// round 16
// speedup vs baseline: 1.1567x; 1.0113x over previous
#include <cuda_runtime.h>
#include <cuda_bf16.h>
#include <cstdint>

#define MDIM 8192
#define KDIM 4096
#define NDIM 11008

// ---------------- static device scratch (no runtime allocation) ----------------
__device__ __align__(256) __nv_bfloat16 g_A[(size_t)MDIM * KDIM];   // 67 MB
__device__ __align__(256) __nv_bfloat16 g_W[(size_t)NDIM * KDIM];   // 90 MB
__device__ __align__(256) float g_xs[MDIM];
__device__ __align__(256) float g_scol[NDIM];
__device__ __align__(256) int   g_mask[KDIM];

// ---------------- PTX helpers ----------------
__device__ __forceinline__ uint32_t smem_u32(const void* p) {
    uint32_t a;
    asm("{ .reg .u64 t; cvta.to.shared.u64 t, %1; cvt.u32.u64 %0, t; }" : "=r"(a) : "l"(p));
    return a;
}
#define SWZ(o) ((o) ^ (((o) >> 3) & 0x70))

__device__ __forceinline__ void cp16(uint32_t s, const void* g) {
    asm volatile("cp.async.cg.shared.global [%0], [%1], 16;" :: "r"(s), "l"(g));
}
#define CP_COMMIT()  asm volatile("cp.async.commit_group;")
#define CP_WAIT(n)   asm volatile("cp.async.wait_group %0;" :: "n"(n))

__device__ __forceinline__ void ldsm_x4(uint32_t& r0, uint32_t& r1, uint32_t& r2,
                                        uint32_t& r3, uint32_t a) {
    asm volatile("ldmatrix.sync.aligned.m8n8.x4.shared.b16 {%0,%1,%2,%3}, [%4];"
                 : "=r"(r0), "=r"(r1), "=r"(r2), "=r"(r3) : "r"(a));
}
__device__ __forceinline__ void mma_bf16(float* c, const uint32_t* a, const uint32_t* b) {
    asm volatile("mma.sync.aligned.m16n8k16.row.col.f32.bf16.bf16.f32 "
        "{%0,%1,%2,%3}, {%4,%5,%6,%7}, {%8,%9}, {%0,%1,%2,%3};"
        : "+f"(c[0]), "+f"(c[1]), "+f"(c[2]), "+f"(c[3])
        : "r"(a[0]), "r"(a[1]), "r"(a[2]), "r"(a[3]), "r"(b[0]), "r"(b[1]));
}

// ---------------- preprocessing ----------------
__global__ void zmask_k() {
    int i = blockIdx.x * blockDim.x + threadIdx.x;
    if (i < KDIM) g_mask[i] = 0;
}

__global__ void colmask_k(const float* __restrict__ x, const float* __restrict__ sg) {
    float s = *sg;
    const float4* x4 = reinterpret_cast<const float4*>(x);
    size_t n4 = (size_t)MDIM * KDIM / 4;
    for (size_t i = (size_t)blockIdx.x * blockDim.x + threadIdx.x; i < n4;
         i += (size_t)gridDim.x * blockDim.x) {
        float4 v = x4[i];
        int k0 = (int)((i * 4) & (KDIM - 1));
        if (fabsf(v.x) > s) atomicOr(&g_mask[k0 + 0], 1);
        if (fabsf(v.y) > s) atomicOr(&g_mask[k0 + 1], 1);
        if (fabsf(v.z) > s) atomicOr(&g_mask[k0 + 2], 1);
        if (fabsf(v.w) > s) atomicOr(&g_mask[k0 + 3], 1);
    }
}

// per weight row: scol = max|w|/64 ; Qw = rint(w/scol) as bf16 (exact: integers <= 64)
__global__ void __launch_bounds__(256) wquant_k(const float* __restrict__ w) {
    int n = blockIdx.x, t = threadIdx.x;
    const float4* row = reinterpret_cast<const float4*>(w + (size_t)n * KDIM);
    float4 v[4]; float mx = 0.f;
#pragma unroll
    for (int i = 0; i < 4; i++) {
        v[i] = row[t + i * 256];
        mx = fmaxf(mx, fmaxf(fmaxf(fabsf(v[i].x), fabsf(v[i].y)),
                             fmaxf(fabsf(v[i].z), fabsf(v[i].w))));
    }
#pragma unroll
    for (int o = 16; o > 0; o >>= 1) mx = fmaxf(mx, __shfl_xor_sync(0xffffffffu, mx, o));
    __shared__ float wm[8];
    if ((t & 31) == 0) wm[t >> 5] = mx;
    __syncthreads();
    float m2 = wm[0];
#pragma unroll
    for (int i = 1; i < 8; i++) m2 = fmaxf(m2, wm[i]);
    float scale = m2 * (1.f / 64.f);
    float inv = 1.f / scale;
    if (t == 0) g_scol[n] = scale;
    __nv_bfloat162* orow = reinterpret_cast<__nv_bfloat162*>(g_W + (size_t)n * KDIM);
#pragma unroll
    for (int i = 0; i < 4; i++) {
        int f = t + i * 256;
        orow[2 * f + 0] = __floats2bfloat162_rn(rintf(v[i].x * inv), rintf(v[i].y * inv));
        orow[2 * f + 1] = __floats2bfloat162_rn(rintf(v[i].z * inv), rintf(v[i].w * inv));
    }
}

// per x row: xs = max(max|x_in|/127, 1e-8); A = mask? x/xs : rint(x/xs) as bf16
__global__ void __launch_bounds__(256) aquant_k(const float* __restrict__ x) {
    int m = blockIdx.x, t = threadIdx.x;
    const float4* row = reinterpret_cast<const float4*>(x + (size_t)m * KDIM);
    float4 v[4]; int msk[16]; float mx = 0.f;
#pragma unroll
    for (int i = 0; i < 4; i++) {
        int f = t + i * 256;
        v[i] = row[f];
        int kb = f * 4;
        msk[4 * i + 0] = g_mask[kb + 0]; msk[4 * i + 1] = g_mask[kb + 1];
        msk[4 * i + 2] = g_mask[kb + 2]; msk[4 * i + 3] = g_mask[kb + 3];
        if (!msk[4 * i + 0]) mx = fmaxf(mx, fabsf(v[i].x));
        if (!msk[4 * i + 1]) mx = fmaxf(mx, fabsf(v[i].y));
        if (!msk[4 * i + 2]) mx = fmaxf(mx, fabsf(v[i].z));
        if (!msk[4 * i + 3]) mx = fmaxf(mx, fabsf(v[i].w));
    }
#pragma unroll
    for (int o = 16; o > 0; o >>= 1) mx = fmaxf(mx, __shfl_xor_sync(0xffffffffu, mx, o));
    __shared__ float wm[8];
    if ((t & 31) == 0) wm[t >> 5] = mx;
    __syncthreads();
    float m2 = wm[0];
#pragma unroll
    for (int i = 1; i < 8; i++) m2 = fmaxf(m2, wm[i]);
    float s = fmaxf(m2 * (1.f / 127.f), 1e-8f);
    float inv = 1.f / s;
    if (t == 0) g_xs[m] = s;
    __nv_bfloat162* orow = reinterpret_cast<__nv_bfloat162*>(g_A + (size_t)m * KDIM);
#pragma unroll
    for (int i = 0; i < 4; i++) {
        int f = t + i * 256;
        float a0 = v[i].x * inv; if (!msk[4 * i + 0]) a0 = rintf(a0);
        float a1 = v[i].y * inv; if (!msk[4 * i + 1]) a1 = rintf(a1);
        float a2 = v[i].z * inv; if (!msk[4 * i + 2]) a2 = rintf(a2);
        float a3 = v[i].w * inv; if (!msk[4 * i + 3]) a3 = rintf(a3);
        orow[2 * f + 0] = __floats2bfloat162_rn(a0, a1);
        orow[2 * f + 1] = __floats2bfloat162_rn(a2, a3);
    }
}

// -- HMMA GEMM: CTA 128x128, 4 warps, warp tile 64x64, 3 stages, 2 CTAs/SM --
#define BM 128
#define BN 128
#define BK 64
#define STAGES 3
#define KBLKS (KDIM / BK)          // 64
#define TM_TILES (MDIM / BM)       // 64
#define TN_TILES (NDIM / BN)       // 86
#define A_BYTES (BM * 128)         // 16 KB
#define B_BYTES (BN * 128)         // 16 KB
#define STAGE_BYTES (A_BYTES + B_BYTES)    // 32 KB
#define SMEM_TOTAL (STAGES * STAGE_BYTES)  // 96 KB -> 2 CTAs/SM

__device__ __forceinline__ void load_stage(uint32_t sb, int s, int kb,
                                           const __nv_bfloat16* __restrict__ Ab,
                                           const __nv_bfloat16* __restrict__ Bb, int t) {
    uint32_t sa = sb + s * STAGE_BYTES;
    const __nv_bfloat16* gA = Ab + kb * BK;
    const __nv_bfloat16* gB = Bb + kb * BK;
#pragma unroll
    for (int i = 0; i < 16; i++) {
        int c = t + i * 128;               // 2048 chunks of 16 B per stage
        int isB = c >> 10;
        int cc = c & 1023;
        int row = cc >> 3, c16 = cc & 7;   // rows 0..127
        uint32_t soff = sa + isB * A_BYTES + SWZ(row * 128 + c16 * 16);
        const __nv_bfloat16* g = (isB ? gB : gA) + (size_t)row * KDIM + c16 * 8;
        cp16(soff, g);
    }
}

__global__ void __launch_bounds__(128, 2) gemm_k(float* __restrict__ out) {
    extern __shared__ char smem[];
    uint32_t sb = smem_u32(smem);
    int tid = threadIdx.x, wid = tid >> 5, lane = tid & 31;

    // grid swizzle: groups of 8 M-tiles share W traffic in L2
    int pid = blockIdx.x;
    const int GR = 8, per = GR * TN_TILES;
    int gid = pid / per, rem = pid % per;
    int fm = gid * GR;
    int gsz = (TM_TILES - fm < GR) ? (TM_TILES - fm) : GR;
    int tm = fm + rem % gsz;
    int tn = rem / gsz;

    const __nv_bfloat16* Ab = g_A + (size_t)tm * BM * KDIM;
    const __nv_bfloat16* Bb = g_W + (size_t)tn * BN * KDIM;

#pragma unroll
    for (int p = 0; p < STAGES - 1; p++) { load_stage(sb, p, p, Ab, Bb, tid); CP_COMMIT(); }

    int wm = wid & 1, wn = wid >> 1;          // warp tile 64x64 at (wm*64, wn*64)
    float acc[4][8][4];
#pragma unroll
    for (int i = 0; i < 4; i++)
#pragma unroll
        for (int j = 0; j < 8; j++)
#pragma unroll
            for (int k = 0; k < 4; k++) acc[i][j][k] = 0.f;

    // ldmatrix lane addressing (within tile, pre-swizzle)
    int a_row = wm * 64 + (lane & 15);        // + mf*16
    int a_kc  = (lane >> 4) * 8;              // + ks*16
    int b_row = wn * 64 + ((lane >> 4) & 1) * 8 + (lane & 7);  // + p*16
    int b_kc  = ((lane >> 3) & 1) * 8;        // + ks*16

    for (int it = 0; it < KBLKS; ++it) {
        int s = it % STAGES;
        CP_WAIT(STAGES - 2);                  // k-block `it` resident
        __syncthreads();
        int nb = it + STAGES - 1;
        if (nb < KBLKS) load_stage(sb, nb % STAGES, nb, Ab, Bb, tid);
        CP_COMMIT();

        uint32_t sa = sb + s * STAGE_BYTES;
#pragma unroll
        for (int ks = 0; ks < 4; ks++) {
            uint32_t a[4][4], b[8][2];
#pragma unroll
            for (int mf = 0; mf < 4; mf++)
                ldsm_x4(a[mf][0], a[mf][1], a[mf][2], a[mf][3],
                        sa + SWZ((a_row + mf * 16) * 128 + (a_kc + ks * 16) * 2));
#pragma unroll
            for (int p = 0; p < 4; p++) {
                uint32_t r0, r1, r2, r3;
                ldsm_x4(r0, r1, r2, r3,
                        sa + A_BYTES + SWZ((b_row + p * 16) * 128 + (b_kc + ks * 16) * 2));
                b[2 * p][0] = r0; b[2 * p][1] = r1;
                b[2 * p + 1][0] = r2; b[2 * p + 1][1] = r3;
            }
#pragma unroll
            for (int mf = 0; mf < 4; mf++)
#pragma unroll
                for (int nf = 0; nf < 8; nf++)
                    mma_bf16(acc[mf][nf], a[mf], b[nf]);
        }
    }

    // epilogue: y = acc * xs[m] * scol[n]
    int m0 = tm * BM + wm * 64 + (lane >> 2);
    int n0 = tn * BN + wn * 64 + (lane & 3) * 2;
#pragma unroll
    for (int mf = 0; mf < 4; mf++) {
        int r0 = m0 + mf * 16;
        float xs0 = g_xs[r0], xs1 = g_xs[r0 + 8];
#pragma unroll
        for (int nf = 0; nf < 8; nf++) {
            int n = n0 + nf * 8;
            float s0 = g_scol[n], s1 = g_scol[n + 1];
            float2 v0 = { acc[mf][nf][0] * xs0 * s0, acc[mf][nf][1] * xs0 * s1 };
            float2 v1 = { acc[mf][nf][2] * xs1 * s0, acc[mf][nf][3] * xs1 * s1 };
            *reinterpret_cast<float2*>(out + (size_t)r0 * NDIM + n) = v0;
            *reinterpret_cast<float2*>(out + (size_t)(r0 + 8) * NDIM + n) = v1;
        }
    }
}

// ---------------- launcher ----------------
extern "C" void kernel_launch(void* const* d_in, const int* in_sizes, int n_in,
                              void* d_out, int out_size) {
    (void)in_sizes; (void)n_in; (void)out_size;
    const float* x   = (const float*)d_in[0];
    const float* w   = (const float*)d_in[1];
    const float* sig = (const float*)d_in[2];
    float* out = (float*)d_out;

    zmask_k<<<(KDIM + 255) / 256, 256>>>();
    colmask_k<<<2048, 256>>>(x, sig);
    wquant_k<<<NDIM, 256>>>(w);
    aquant_k<<<MDIM, 256>>>(x);

    cudaFuncSetAttribute(gemm_k, cudaFuncAttributeMaxDynamicSharedMemorySize, SMEM_TOTAL);
    gemm_k<<<TM_TILES * TN_TILES, 128, SMEM_TOTAL>>>(out);
}